// round 3
// baseline (speedup 1.0000x reference)
#include <cuda_runtime.h>
#include <cuda_bf16.h>

// Problem constants (fixed by the reference)
#define NND   100000      // nodes
#define NED   50000       // hyperedges
#define NNZE  1280000     // incidence nnz
#define FT    128
#define HID   64
#define NCLS  32
#define NGR   256

#define XSTR  68          // padded shared row stride (floats)
#define NB_N  1563        // ceil(NND/64)
#define NB_E  782         // ceil(NED/64)

// ---------------- device scratch (static; no allocation allowed) -------------
__device__ float g_x   [NND * HID];
__device__ float g_x0  [NND * HID];
__device__ float g_h   [NND * HID];
__device__ float g_y   [NED * HID];
__device__ float g_cls [NND * NCLS];
__device__ int   g_noff[NND + 1];
__device__ int   g_goff[NGR + 1];
__device__ int   g_eoff[NED + 1];
__device__ int   g_cur [NED];
__device__ int   g_esrc[NNZE];

// ---------------- helpers ----------------------------------------------------
__device__ __forceinline__ int lower_bound_i(const int* __restrict__ a, int n, int key) {
    int lo = 0, hi = n;
    while (lo < hi) {
        int mid = (lo + hi) >> 1;
        if (a[mid] < key) lo = mid + 1; else hi = mid;
    }
    return lo;
}

__global__ void k_node_off(const int* __restrict__ src) {
    int v = blockIdx.x * blockDim.x + threadIdx.x;
    if (v <= NND) g_noff[v] = lower_bound_i(src, NNZE, v);
}

__global__ void k_graph_off(const int* __restrict__ batch) {
    int g = threadIdx.x;
    if (g <= NGR) g_goff[g] = lower_bound_i(batch, NND, g);
}

// ---------------- dst-CSR build (once per launch) -----------------------------
__global__ void k_zero_cnt() {
    int i = blockIdx.x * blockDim.x + threadIdx.x;
    if (i < NED) g_cur[i] = 0;
}
__global__ void k_hist(const int* __restrict__ dst) {
    int i = blockIdx.x * blockDim.x + threadIdx.x;
    if (i < NNZE) atomicAdd(&g_cur[dst[i]], 1);
}
// single-block exclusive scan of g_cur -> g_eoff; leaves g_cur = eoff (cursor)
__global__ void k_scan() {
    __shared__ int part[1024];
    const int CH = (NED + 1023) / 1024;       // 49
    const int t = threadIdx.x;
    const int beg = t * CH;
    const int end = min(beg + CH, NED);
    int s = 0;
    for (int i = beg; i < end; i++) s += g_cur[i];
    part[t] = s;
    __syncthreads();
    for (int off = 1; off < 1024; off <<= 1) {
        int v = (t >= off) ? part[t - off] : 0;
        __syncthreads();
        part[t] += v;
        __syncthreads();
    }
    int run = (t == 0) ? 0 : part[t - 1];
    for (int i = beg; i < end; i++) {
        int c = g_cur[i];
        g_eoff[i] = run;
        g_cur[i]  = run;
        run += c;
    }
    if (t == 1023) g_eoff[NED] = run;
}
__global__ void k_fill(const int* __restrict__ src, const int* __restrict__ dst) {
    int i = blockIdx.x * blockDim.x + threadIdx.x;
    if (i < NNZE) {
        int pos = atomicAdd(&g_cur[dst[i]], 1);
        g_esrc[pos] = src[i];
    }
}

// ---------------- 4x8 register-tiled GEMM over a 64-row tile ------------------
// block (8,16): tx covers 64 cols (8 each), ty*4+r covers 64 rows
__device__ __forceinline__ void gemm48(const float* __restrict__ xs,
                                       const float* __restrict__ Ws,
                                       float acc[4][8], int tx, int ty) {
    #pragma unroll 4
    for (int k = 0; k < 64; k += 4) {
        float w[4][8];
        #pragma unroll
        for (int kk = 0; kk < 4; kk++) {
            *reinterpret_cast<float4*>(&w[kk][0]) =
                *reinterpret_cast<const float4*>(&Ws[(k + kk) * 64 + tx * 8]);
            *reinterpret_cast<float4*>(&w[kk][4]) =
                *reinterpret_cast<const float4*>(&Ws[(k + kk) * 64 + tx * 8 + 4]);
        }
        #pragma unroll
        for (int r = 0; r < 4; r++) {
            float xv[4];
            *reinterpret_cast<float4*>(xv) =
                *reinterpret_cast<const float4*>(&xs[(ty * 4 + r) * XSTR + k]);
            #pragma unroll
            for (int kk = 0; kk < 4; kk++)
                #pragma unroll
                for (int c = 0; c < 8; c++)
                    acc[r][c] = fmaf(xv[kk], w[kk][c], acc[r][c]);
        }
    }
}

__device__ __forceinline__ void zero_acc(float acc[4][8]) {
    #pragma unroll
    for (int r = 0; r < 4; r++)
        #pragma unroll
        for (int c = 0; c < 8; c++) acc[r][c] = 0.f;
}

// load a 64-row x 64-col tile (row stride 64) into padded shared (128 threads)
__device__ __forceinline__ void load_tile64(float* __restrict__ xs,
                                            const float* __restrict__ g,
                                            int row0, int nrows, int t) {
    #pragma unroll
    for (int i = t; i < 64 * 16; i += 128) {
        int r  = i >> 4;
        int c4 = (i & 15) * 4;
        float4 v = make_float4(0.f, 0.f, 0.f, 0.f);
        int row = row0 + r;
        if (row < nrows) v = *reinterpret_cast<const float4*>(&g[(size_t)row * 64 + c4]);
        *reinterpret_cast<float4*>(&xs[r * XSTR + c4]) = v;
    }
}

// ---------------- input layer: x = relu(X @ W_in + b_in) ---------------------
__global__ void __launch_bounds__(128) k_in(const float* __restrict__ X,
                                            const float* __restrict__ W,
                                            const float* __restrict__ b) {
    __shared__ float Ws[64 * 64];
    __shared__ float xs[64 * XSTR];
    __shared__ float bs[64];
    const int tx = threadIdx.x, ty = threadIdx.y;
    const int t = ty * 8 + tx;
    const int row0 = blockIdx.x * 64;
    if (t < 64) bs[t] = b[t];

    float acc[4][8];
    zero_acc(acc);

    for (int ch = 0; ch < 2; ch++) {
        __syncthreads();
        for (int i = t; i < 64 * 64; i += 128) Ws[i] = W[ch * 64 * 64 + i];
        #pragma unroll
        for (int i = t; i < 64 * 16; i += 128) {
            int r = i >> 4, c4 = (i & 15) * 4;
            float4 v = make_float4(0.f, 0.f, 0.f, 0.f);
            int row = row0 + r;
            if (row < NND) v = *reinterpret_cast<const float4*>(&X[(size_t)row * FT + ch * 64 + c4]);
            *reinterpret_cast<float4*>(&xs[r * XSTR + c4]) = v;
        }
        __syncthreads();
        gemm48(xs, Ws, acc, tx, ty);
    }

    #pragma unroll
    for (int r = 0; r < 4; r++) {
        int row = row0 + ty * 4 + r;
        if (row < NND) {
            float o[8];
            #pragma unroll
            for (int c = 0; c < 8; c++) o[c] = fmaxf(acc[r][c] + bs[tx * 8 + c], 0.f);
            *reinterpret_cast<float4*>(&g_x [(size_t)row * 64 + tx * 8])     = *reinterpret_cast<float4*>(&o[0]);
            *reinterpret_cast<float4*>(&g_x [(size_t)row * 64 + tx * 8 + 4]) = *reinterpret_cast<float4*>(&o[4]);
            *reinterpret_cast<float4*>(&g_x0[(size_t)row * 64 + tx * 8])     = *reinterpret_cast<float4*>(&o[0]);
            *reinterpret_cast<float4*>(&g_x0[(size_t)row * 64 + tx * 8 + 4]) = *reinterpret_cast<float4*>(&o[4]);
        }
    }
}

// ---------------- h = relu(x@W1a+b1a) @ W1b + b1b ----------------------------
__global__ void __launch_bounds__(128) k_h(const float* __restrict__ Wa,
                                           const float* __restrict__ ba,
                                           const float* __restrict__ Wb,
                                           const float* __restrict__ bb) {
    __shared__ float Ws[64 * 64];
    __shared__ float xs[64 * XSTR];
    __shared__ float bas[64], bbs[64];
    const int tx = threadIdx.x, ty = threadIdx.y;
    const int t = ty * 8 + tx;
    const int row0 = blockIdx.x * 64;
    for (int i = t; i < 64 * 64; i += 128) Ws[i] = Wa[i];
    if (t < 64) { bas[t] = ba[t]; bbs[t] = bb[t]; }
    load_tile64(xs, g_x, row0, NND, t);
    __syncthreads();

    float acc[4][8];
    zero_acc(acc);
    gemm48(xs, Ws, acc, tx, ty);
    __syncthreads();

    #pragma unroll
    for (int r = 0; r < 4; r++)
        #pragma unroll
        for (int c = 0; c < 8; c++)
            xs[(ty * 4 + r) * XSTR + tx * 8 + c] = fmaxf(acc[r][c] + bas[tx * 8 + c], 0.f);
    for (int i = t; i < 64 * 64; i += 128) Ws[i] = Wb[i];
    __syncthreads();

    float acc2[4][8];
    zero_acc(acc2);
    gemm48(xs, Ws, acc2, tx, ty);

    #pragma unroll
    for (int r = 0; r < 4; r++) {
        int row = row0 + ty * 4 + r;
        if (row < NND) {
            float o[8];
            #pragma unroll
            for (int c = 0; c < 8; c++) o[c] = acc2[r][c] + bbs[tx * 8 + c];
            *reinterpret_cast<float4*>(&g_h[(size_t)row * 64 + tx * 8])     = *reinterpret_cast<float4*>(&o[0]);
            *reinterpret_cast<float4*>(&g_h[(size_t)row * 64 + tx * 8 + 4]) = *reinterpret_cast<float4*>(&o[4]);
        }
    }
}

// ---------------- edge: Y[e] = mean_{s in e} h[s]  @ W2b ----------------------
__global__ void __launch_bounds__(128) k_edge(const float* __restrict__ W2) {
    __shared__ float Ws[64 * 64];
    __shared__ float xs[64 * XSTR];
    __shared__ int offs[65];
    const int tx = threadIdx.x, ty = threadIdx.y;
    const int t = ty * 8 + tx;
    const int row0 = blockIdx.x * 64;
    for (int i = t; i < 64 * 64; i += 128) Ws[i] = W2[64 * 64 + i];   // W2b
    if (t < 65) offs[t] = g_eoff[min(row0 + t, NED)];
    __syncthreads();

    // gather-mean rows into xs
    #pragma unroll
    for (int r = 0; r < 4; r++) {
        const int lr = ty * 4 + r;
        const int e = row0 + lr;
        float z[8];
        #pragma unroll
        for (int c = 0; c < 8; c++) z[c] = 0.f;
        int cnt = 0;
        if (e < NED) {
            const int beg = offs[lr], end = offs[lr + 1];
            cnt = end - beg;
            for (int j = beg; j < end; j++) {
                const int s = __ldg(&g_esrc[j]);
                const float4 a = *reinterpret_cast<const float4*>(&g_h[(size_t)s * 64 + tx * 8]);
                const float4 b = *reinterpret_cast<const float4*>(&g_h[(size_t)s * 64 + tx * 8 + 4]);
                z[0] += a.x; z[1] += a.y; z[2] += a.z; z[3] += a.w;
                z[4] += b.x; z[5] += b.y; z[6] += b.z; z[7] += b.w;
            }
        }
        const float inv = (cnt > 0) ? 1.f / (float)cnt : 0.f;
        #pragma unroll
        for (int c = 0; c < 8; c++) xs[lr * XSTR + tx * 8 + c] = z[c] * inv;
    }
    __syncthreads();

    float acc[4][8];
    zero_acc(acc);
    gemm48(xs, Ws, acc, tx, ty);

    #pragma unroll
    for (int r = 0; r < 4; r++) {
        int row = row0 + ty * 4 + r;
        if (row < NED) {
            *reinterpret_cast<float4*>(&g_y[(size_t)row * 64 + tx * 8])     = *reinterpret_cast<float4*>(&acc[r][0]);
            *reinterpret_cast<float4*>(&g_y[(size_t)row * 64 + tx * 8 + 4]) = *reinterpret_cast<float4*>(&acc[r][4]);
        }
    }
}

// ---------------- combine: Xv = x@W2a + b2 + mean_j Y[dst_j]; residual; W3; relu
__global__ void __launch_bounds__(128) k_combine(const float* __restrict__ W2,
                                                 const float* __restrict__ b2,
                                                 const float* __restrict__ W3,
                                                 const float* __restrict__ b3,
                                                 const int* __restrict__ dst) {
    __shared__ float Ws[64 * 64];
    __shared__ float xs[64 * XSTR];
    __shared__ float b2s[64], b3s[64];
    __shared__ int offs[65];
    const int tx = threadIdx.x, ty = threadIdx.y;
    const int t = ty * 8 + tx;
    const int row0 = blockIdx.x * 64;
    for (int i = t; i < 64 * 64; i += 128) Ws[i] = W2[i];    // W2a
    if (t < 64) { b2s[t] = b2[t]; b3s[t] = b3[t]; }
    if (t < 65) offs[t] = g_noff[min(row0 + t, NND)];
    load_tile64(xs, g_x, row0, NND, t);
    __syncthreads();

    float acc[4][8];
    zero_acc(acc);
    gemm48(xs, Ws, acc, tx, ty);         // x @ W2a
    __syncthreads();                     // xs free

    // gather mean of Y over node's edges, compose u into xs
    #pragma unroll
    for (int r = 0; r < 4; r++) {
        const int lr = ty * 4 + r;
        const int v = row0 + lr;
        float z[8];
        #pragma unroll
        for (int c = 0; c < 8; c++) z[c] = 0.f;
        int cnt = 0;
        if (v < NND) {
            const int beg = offs[lr], end = offs[lr + 1];
            cnt = end - beg;
            for (int j = beg; j < end; j++) {
                const int d = __ldg(&dst[j]);
                const float4 a = *reinterpret_cast<const float4*>(&g_y[(size_t)d * 64 + tx * 8]);
                const float4 b = *reinterpret_cast<const float4*>(&g_y[(size_t)d * 64 + tx * 8 + 4]);
                z[0] += a.x; z[1] += a.y; z[2] += a.z; z[3] += a.w;
                z[4] += b.x; z[5] += b.y; z[6] += b.z; z[7] += b.w;
            }
        }
        const float inv = (cnt > 0) ? 1.f / (float)cnt : 0.f;
        float x0a[8] = {0.f, 0.f, 0.f, 0.f, 0.f, 0.f, 0.f, 0.f};
        if (v < NND) {
            *reinterpret_cast<float4*>(&x0a[0]) = *reinterpret_cast<const float4*>(&g_x0[(size_t)v * 64 + tx * 8]);
            *reinterpret_cast<float4*>(&x0a[4]) = *reinterpret_cast<const float4*>(&g_x0[(size_t)v * 64 + tx * 8 + 4]);
        }
        #pragma unroll
        for (int c = 0; c < 8; c++) {
            float xv = 0.f;
            if (cnt > 0) xv = acc[r][c] + b2s[tx * 8 + c] + z[c] * inv;
            xs[lr * XSTR + tx * 8 + c] = 0.5f * xv + 0.5f * x0a[c];
        }
    }
    for (int i = t; i < 64 * 64; i += 128) Ws[i] = W3[i];
    __syncthreads();

    float acc2[4][8];
    zero_acc(acc2);
    gemm48(xs, Ws, acc2, tx, ty);

    #pragma unroll
    for (int r = 0; r < 4; r++) {
        int row = row0 + ty * 4 + r;
        if (row < NND) {
            float o[8];
            #pragma unroll
            for (int c = 0; c < 8; c++) o[c] = fmaxf(acc2[r][c] + b3s[tx * 8 + c], 0.f);
            *reinterpret_cast<float4*>(&g_x[(size_t)row * 64 + tx * 8])     = *reinterpret_cast<float4*>(&o[0]);
            *reinterpret_cast<float4*>(&g_x[(size_t)row * 64 + tx * 8 + 4]) = *reinterpret_cast<float4*>(&o[4]);
        }
    }
}

// ---------------- classifier: cls = relu(x@Wc1+bc1) @ Wc2 + bc2 ---------------
__global__ void __launch_bounds__(128) k_cls(const float* __restrict__ W1,
                                             const float* __restrict__ b1,
                                             const float* __restrict__ W2,
                                             const float* __restrict__ b2) {
    __shared__ float W1s[64 * 64];
    __shared__ float W2s[64 * 32];
    __shared__ float xs[64 * XSTR];
    __shared__ float b1s[64], b2s[32];
    const int tx = threadIdx.x, ty = threadIdx.y;
    const int t = ty * 8 + tx;
    const int row0 = blockIdx.x * 64;
    for (int i = t; i < 64 * 64; i += 128) W1s[i] = W1[i];
    for (int i = t; i < 64 * 32; i += 128) W2s[i] = W2[i];
    if (t < 64) b1s[t] = b1[t];
    if (t < 32) b2s[t] = b2[t];
    load_tile64(xs, g_x, row0, NND, t);
    __syncthreads();

    float acc[4][8];
    zero_acc(acc);
    gemm48(xs, W1s, acc, tx, ty);
    __syncthreads();
    #pragma unroll
    for (int r = 0; r < 4; r++)
        #pragma unroll
        for (int c = 0; c < 8; c++)
            xs[(ty * 4 + r) * XSTR + tx * 8 + c] = fmaxf(acc[r][c] + b1s[tx * 8 + c], 0.f);
    __syncthreads();

    // GEMM2: 64 -> 32, 4 rows x 4 cols per thread (tx covers 32 cols)
    float acc2[4][4];
    #pragma unroll
    for (int r = 0; r < 4; r++)
        #pragma unroll
        for (int c = 0; c < 4; c++) acc2[r][c] = 0.f;
    #pragma unroll 4
    for (int k = 0; k < 64; k += 4) {
        float w[4][4];
        #pragma unroll
        for (int kk = 0; kk < 4; kk++)
            *reinterpret_cast<float4*>(w[kk]) =
                *reinterpret_cast<const float4*>(&W2s[(k + kk) * 32 + tx * 4]);
        #pragma unroll
        for (int r = 0; r < 4; r++) {
            float xv[4];
            *reinterpret_cast<float4*>(xv) =
                *reinterpret_cast<const float4*>(&xs[(ty * 4 + r) * XSTR + k]);
            #pragma unroll
            for (int kk = 0; kk < 4; kk++)
                #pragma unroll
                for (int c = 0; c < 4; c++)
                    acc2[r][c] = fmaf(xv[kk], w[kk][c], acc2[r][c]);
        }
    }
    #pragma unroll
    for (int r = 0; r < 4; r++) {
        int row = row0 + ty * 4 + r;
        if (row < NND) {
            float o[4];
            #pragma unroll
            for (int c = 0; c < 4; c++) o[c] = acc2[r][c] + b2s[tx * 4 + c];
            *reinterpret_cast<float4*>(&g_cls[(size_t)row * 32 + tx * 4]) = *reinterpret_cast<float4*>(o);
        }
    }
}

// ---------------- readout: per-graph mean over sorted all_batch ---------------
__global__ void k_readout(float* __restrict__ out) {
    __shared__ float part[8][NCLS];
    const int g = blockIdx.x;
    const int tx = threadIdx.x, ty = threadIdx.y;  // (32, 8)
    const int beg = g_goff[g], end = g_goff[g + 1];
    float s = 0.f;
    for (int j = beg + ty; j < end; j += 8)
        s += g_cls[(size_t)j * NCLS + tx];
    part[ty][tx] = s;
    __syncthreads();
    if (ty == 0) {
        float tot = 0.f;
        #pragma unroll
        for (int r = 0; r < 8; r++) tot += part[r][tx];
        const int c = end - beg;
        out[g * NCLS + tx] = tot / fmaxf((float)c, 1.f);
    }
}

// ---------------- launch ------------------------------------------------------
extern "C" void kernel_launch(void* const* d_in, const int* in_sizes, int n_in,
                              void* d_out, int out_size) {
    const float* X       = (const float*)d_in[0];
    const int*   v2e_src = (const int*)  d_in[1];
    const int*   v2e_dst = (const int*)  d_in[2];
    const int*   batch   = (const int*)  d_in[3];
    const float* W_in    = (const float*)d_in[4];
    const float* b_in    = (const float*)d_in[5];
    const float* W1a     = (const float*)d_in[6];
    const float* b1a     = (const float*)d_in[7];
    const float* W1b     = (const float*)d_in[8];
    const float* b1b     = (const float*)d_in[9];
    const float* W2      = (const float*)d_in[10];
    const float* b2      = (const float*)d_in[11];
    const float* W3      = (const float*)d_in[12];
    const float* b3      = (const float*)d_in[13];
    const float* Wc1     = (const float*)d_in[14];
    const float* bc1     = (const float*)d_in[15];
    const float* Wc2     = (const float*)d_in[16];
    const float* bc2     = (const float*)d_in[17];
    float* out = (float*)d_out;

    const dim3 blk(8, 16);

    // CSR builds (once per launch)
    k_node_off<<<(NND + 1 + 255) / 256, 256>>>(v2e_src);
    k_graph_off<<<1, NGR + 1>>>(batch);
    k_zero_cnt<<<(NED + 255) / 256, 256>>>();
    k_hist<<<(NNZE + 255) / 256, 256>>>(v2e_dst);
    k_scan<<<1, 1024>>>();
    k_fill<<<(NNZE + 255) / 256, 256>>>(v2e_src, v2e_dst);

    k_in<<<NB_N, blk>>>(X, W_in, b_in);

    for (int layer = 0; layer < 2; layer++) {
        k_h<<<NB_N, blk>>>(W1a, b1a, W1b, b1b);
        k_edge<<<NB_E, blk>>>(W2);
        k_combine<<<NB_N, blk>>>(W2, b2, W3, b3, v2e_dst);
    }

    k_cls<<<NB_N, blk>>>(Wc1, bc1, Wc2, bc2);
    k_readout<<<NGR, dim3(32, 8)>>>(out);
}